// round 9
// baseline (speedup 1.0000x reference)
#include <cuda_runtime.h>
#include <math.h>

#define S_LEN 512
#define HID   256
#define NH    8
#define HD    32
#define SCALE_F 0.17677669529663687f   // 1/sqrt(32)
#define PI_F    3.14159265358979323846f

// Scratch (no allocations allowed): qkv projections + attention context
__device__ float g_qkv[3 * S_LEN * HID];
__device__ float g_ctx[S_LEN * HID];

typedef unsigned long long ull;

__device__ __forceinline__ ull pack2(float lo, float hi) {
    ull r; asm("mov.b64 %0, {%1, %2};" : "=l"(r) : "f"(lo), "f"(hi)); return r;
}
__device__ __forceinline__ void unpack2(ull v, float& lo, float& hi) {
    asm("mov.b64 {%0, %1}, %2;" : "=f"(lo), "=f"(hi) : "l"(v));
}
#define FMA2(d, a, b, c) asm("fma.rn.f32x2 %0, %1, %2, %3;" : "=l"(d) : "l"(a), "l"(b), "l"(c))
#define MUL2(d, a, b)    asm("mul.rn.f32x2 %0, %1, %2;"     : "=l"(d) : "l"(a), "l"(b))
#define ADD2(d, a, b)    asm("add.rn.f32x2 %0, %1, %2;"     : "=l"(d) : "l"(a), "l"(b))
#define XOR64(d, a, b)   asm("xor.b64 %0, %1, %2;"          : "=l"(d) : "l"(a), "l"(b))

// ---------------------------------------------------------------------------
// GEMM: C[m,n] = bias[n] + sum_c A[m,c]*W[n,c].  A:[M,256] W:[N,256] C ld=256.
// Tile 32x32, 128 threads, 2m x 4n per thread. K staged in TWO 128-wide
// slices (52KB dyn smem): only 3 __syncthreads per block; each slice runs a
// barrier-free 128-deep inner loop (2x LDS.64 broadcast + 1x LDS.128 + 4 FMA2).
// ---------------------------------------------------------------------------
#define GK 256
#define GEMM_SMEM (128 * 33 * 8 + 128 * 36 * 4)   // As2 33792B + Ws 18432B

__device__ __forceinline__ void gemm_body(
    const float* __restrict__ A, const float* __restrict__ W,
    const float* __restrict__ bias, float* __restrict__ C)
{
    extern __shared__ char gsm[];
    ull*   As2 = reinterpret_cast<ull*>(gsm);            // [128][33] (a,a) pairs
    float* Ws  = reinterpret_cast<float*>(gsm + 128 * 33 * 8);  // [128][36]

    const int tid = threadIdx.x;       // 0..127
    const int m0 = blockIdx.y * 32;
    const int n0 = blockIdx.x * 32;
    const int tm = tid >> 3;           // 0..15 -> rows 2tm, 2tm+1
    const int tn = tid & 7;            // 0..7  -> cols 4tn..4tn+3
    const int sr = tid >> 2;           // staging row 0..31
    const int sq = tid & 3;            // staging col group

    ull acc00 = 0ull, acc01 = 0ull, acc10 = 0ull, acc11 = 0ull;

#pragma unroll 1
    for (int half = 0; half < 2; half++) {
        const int k0 = half * 128;
        if (half) __syncthreads();
        // stage A[m0..+31][k0..+127] (splatted) and W[n0..+31][k0..+127]
#pragma unroll
        for (int seg = 0; seg < 8; seg++) {
            int k = sq * 32 + seg * 4;
            float4 a4 = *reinterpret_cast<const float4*>(A + (m0 + sr) * GK + k0 + k);
            float4 w4 = *reinterpret_cast<const float4*>(W + (n0 + sr) * GK + k0 + k);
            As2[(k + 0) * 33 + sr] = pack2(a4.x, a4.x);
            As2[(k + 1) * 33 + sr] = pack2(a4.y, a4.y);
            As2[(k + 2) * 33 + sr] = pack2(a4.z, a4.z);
            As2[(k + 3) * 33 + sr] = pack2(a4.w, a4.w);
            Ws[(k + 0) * 36 + sr] = w4.x;
            Ws[(k + 1) * 36 + sr] = w4.y;
            Ws[(k + 2) * 36 + sr] = w4.z;
            Ws[(k + 3) * 36 + sr] = w4.w;
        }
        __syncthreads();
#pragma unroll 16
        for (int kk = 0; kk < 128; kk++) {
            ull a0 = As2[kk * 33 + 2 * tm];
            ull a1 = As2[kk * 33 + 2 * tm + 1];
            ulonglong2 w = *reinterpret_cast<const ulonglong2*>(Ws + kk * 36 + 4 * tn);
            FMA2(acc00, a0, w.x, acc00);
            FMA2(acc01, a0, w.y, acc01);
            FMA2(acc10, a1, w.x, acc10);
            FMA2(acc11, a1, w.y, acc11);
        }
    }

    float4 b4 = *reinterpret_cast<const float4*>(bias + n0 + 4 * tn);
    float x0, x1, x2, x3;
    unpack2(acc00, x0, x1); unpack2(acc01, x2, x3);
    {
        float4 o; o.x = x0 + b4.x; o.y = x1 + b4.y; o.z = x2 + b4.z; o.w = x3 + b4.w;
        *reinterpret_cast<float4*>(&C[(m0 + 2 * tm) * HID + n0 + 4 * tn]) = o;
    }
    unpack2(acc10, x0, x1); unpack2(acc11, x2, x3);
    {
        float4 o; o.x = x0 + b4.x; o.y = x1 + b4.y; o.z = x2 + b4.z; o.w = x3 + b4.w;
        *reinterpret_cast<float4*>(&C[(m0 + 2 * tm + 1) * HID + n0 + 4 * tn]) = o;
    }
}

__global__ void __launch_bounds__(128)
gemm_qkv_kernel(const float* __restrict__ x,
                const float* __restrict__ wq, const float* __restrict__ bq,
                const float* __restrict__ wk, const float* __restrict__ bk,
                const float* __restrict__ wv, const float* __restrict__ bv)
{
    const int z = blockIdx.z;
    const float* W = (z == 0) ? wq : ((z == 1) ? wk : wv);
    const float* b = (z == 0) ? bq : ((z == 1) ? bk : bv);
    float* C = g_qkv + z * (S_LEN * HID);
    gemm_body(x, W, b, C);
}

__global__ void __launch_bounds__(128)
gemm_out_kernel(const float* __restrict__ wo, const float* __restrict__ bo,
                float* __restrict__ out)
{
    gemm_body(g_ctx, wo, bo, out);
}

// ---------------------------------------------------------------------------
// Attention. Grid: (32 i-tiles, 8 heads), 256 threads = 8 warps x 32 d.
// Each warp owns TWO i-rows (i0 = bx*16 + 2r, i1 = i0+1) sharing one V load.
// logit X_j = K0*cos(theta0 - j*omega), K0 = SCALE*sigmoid(k) <= 0.177.
// Weight p = 1 + b*X + X^2/2 with minimax slope b = 1 + K0^2/8
// (equioscillated cubic residual: |err| <= K0^3/24 = 2.3e-4 worst case).
// Numerator: sum (p-1)*V via Chebyshev phasor recurrence; sum V precomputed.
// Denominator closed form via Dirichlet sums D1, D2.
// ---------------------------------------------------------------------------
#define ATTN_SMEM (256 * 32 * 8 + 8 * 32 * 8)   // V pairs + partial sums

__global__ void __launch_bounds__(256)
attn_kernel()
{
    extern __shared__ ull Vs[];           // [256][32] j-pairs, then Ps[8][32]
    ull* Ps = Vs + 256 * 32;
    const int h   = blockIdx.y;
    const int tid = threadIdx.x;
    const int d   = tid & 31;
    const int r   = tid >> 5;             // warp id
    const int i0  = blockIdx.x * 16 + 2 * r;
    const int i1  = i0 + 1;

    const float* gq = g_qkv;
    const float* gk = g_qkv + S_LEN * HID;
    const float* gv = g_qkv + 2 * S_LEN * HID;

    // Stage V[h,:,:] as (even,odd) pairs + per-group partial sums of V.
    {
        float sve = 0.0f, svo = 0.0f;
#pragma unroll 4
        for (int kk = 0; kk < 32; kk++) {
            int k = r * 32 + kk;
            float v0 = gv[(2 * k)     * HID + h * HD + d];
            float v1 = gv[(2 * k + 1) * HID + h * HD + d];
            Vs[k * 32 + d] = pack2(v0, v1);
            sve += v0; svo += v1;
        }
        Ps[r * 32 + d] = pack2(sve, svo);
    }

    const int col = h * HD + d;

    // Per-i wave state
    ull X[2], NX[2], C2v[2], B2[2], acc[2];
    float sumw[2];
#pragma unroll
    for (int u = 0; u < 2; u++) {
        const int i = (u == 0) ? i0 : i1;
        const float qv = gq[i * HID + col];
        const float kv = gk[i * HID + col];
        const float vv = gv[i * HID + col];

        const float omega = PI_F / (1.0f + expf(-qv));   // sigmoid(q)*pi
        const float amp   = 1.0f / (1.0f + expf(-kv));   // sigmoid(k)
        const float phase = PI_F * tanhf(vv);            // tanh(v)*pi
        const float K0    = SCALE_F * amp;
        const float bmin  = 1.0f + K0 * K0 * 0.125f;     // minimax slope

        const float th0 = omega * (float)i + phase;      // theta at j=0
        float s0, c0, sw, cw;
        sincosf(th0, &s0, &c0);
        sincosf(omega, &sw, &cw);
        const float c2w = cw * cw - sw * sw;             // cos(2w)
        const float s2w = 2.0f * sw * cw;                // sin(2w)
        // X_0 lanes: j=0, j=1 ; X_{-1} lanes: j=-2, j=-1
        const float x0e = K0 * c0;
        const float x0o = K0 * (c0 * cw + s0 * sw);
        const float xme = K0 * (c0 * c2w - s0 * s2w);
        const float xmo = K0 * (c0 * cw - s0 * sw);

        // Denominator: sum_j (1 + b*x_j + x_j^2/2), j=0..511
        // Dm = cos(m*th0 - 255.5*m*w) * sin(256*m*w) / sin(m*w/2)
        const float sb2 = sinf(0.5f * omega);
        const float D1 = cosf(th0 - 255.5f * omega) * sinf(256.0f * omega) / sb2;
        const float D2 = cosf(2.0f * th0 - 511.0f * omega) * sinf(512.0f * omega) / sw;
        sumw[u] = 512.0f + bmin * K0 * D1
                + 0.5f * K0 * K0 * (256.0f + 0.5f * D2);

        X[u]   = pack2(x0e, x0o);
        NX[u]  = pack2(-xme, -xmo);
        C2v[u] = pack2(2.0f * c2w, 2.0f * c2w);
        B2[u]  = pack2(bmin, bmin);
        acc[u] = 0ull;
    }

    const ull SMASK = 0x8000000080000000ULL;
    ull P2 = pack2(0.5f, 0.5f);

    __syncthreads();

    // sum of V over all j for this (h,d)
    float svE = 0.0f, svO = 0.0f;
#pragma unroll
    for (int g = 0; g < 8; g++) {
        float pe, po;
        unpack2(Ps[g * 32 + d], pe, po);
        svE += pe; svO += po;
    }

    const ull* vp = Vs + d;

#pragma unroll 8
    for (int k = 0; k < 256; k++) {
        ull V2 = vp[k * 32];
#pragma unroll
        for (int u = 0; u < 2; u++) {
            ull rr, t, Xn;
            // p-1 = x*(b + x/2)
            FMA2(rr, X[u], P2, B2[u]);
            MUL2(t, X[u], V2);
            FMA2(acc[u], rr, t, acc[u]);
            // Chebyshev: X_{k+1} = 2cos(2w)*X_k + (-X_{k-1})
            FMA2(Xn, C2v[u], X[u], NX[u]);
            XOR64(NX[u], X[u], SMASK);
            X[u] = Xn;
        }
    }

    float ae, ao;
    unpack2(acc[0], ae, ao);
    g_ctx[i0 * HID + col] = (svE + svO + ae + ao) / sumw[0];
    unpack2(acc[1], ae, ao);
    g_ctx[i1 * HID + col] = (svE + svO + ae + ao) / sumw[1];
}

// ---------------------------------------------------------------------------
extern "C" void kernel_launch(void* const* d_in, const int* in_sizes, int n_in,
                              void* d_out, int out_size)
{
    const float* x  = (const float*)d_in[0];
    const float* wq = (const float*)d_in[1];
    const float* bq = (const float*)d_in[2];
    const float* wk = (const float*)d_in[3];
    const float* bk = (const float*)d_in[4];
    const float* wv = (const float*)d_in[5];
    const float* bv = (const float*)d_in[6];
    const float* wo = (const float*)d_in[7];
    const float* bo = (const float*)d_in[8];
    float* out = (float*)d_out;

    cudaFuncSetAttribute(gemm_qkv_kernel, cudaFuncAttributeMaxDynamicSharedMemorySize, GEMM_SMEM);
    cudaFuncSetAttribute(gemm_out_kernel, cudaFuncAttributeMaxDynamicSharedMemorySize, GEMM_SMEM);
    cudaFuncSetAttribute(attn_kernel, cudaFuncAttributeMaxDynamicSharedMemorySize, ATTN_SMEM);

    // QKV projections: (8 n) x (16 m) x 3 = 384 blocks of 128 threads
    gemm_qkv_kernel<<<dim3(HID / 32, S_LEN / 32, 3), 128, GEMM_SMEM>>>(x, wq, bq, wk, bk, wv, bv);

    // Attention: 32 i-tiles x 8 heads
    attn_kernel<<<dim3(S_LEN / 16, NH), 256, ATTN_SMEM>>>();

    // Output projection: 128 blocks
    gemm_out_kernel<<<dim3(HID / 32, S_LEN / 32), 128, GEMM_SMEM>>>(wo, bo, out);
}

// round 13
// speedup vs baseline: 1.1047x; 1.1047x over previous
#include <cuda_runtime.h>
#include <math.h>

#define S_LEN 512
#define HID   256
#define NH    8
#define HD    32
#define SCALE_F 0.17677669529663687f   // 1/sqrt(32)
#define PI_F    3.14159265358979323846f

// Scratch (no allocations allowed). Split-K partial buffers for qkv and out.
__device__ float g_qkvA[3 * S_LEN * HID];
__device__ float g_qkvB[3 * S_LEN * HID];
__device__ float g_ctx[S_LEN * HID];
__device__ float g_outA[S_LEN * HID];
__device__ float g_outB[S_LEN * HID];

typedef unsigned long long ull;

__device__ __forceinline__ ull pack2(float lo, float hi) {
    ull r; asm("mov.b64 %0, {%1, %2};" : "=l"(r) : "f"(lo), "f"(hi)); return r;
}
__device__ __forceinline__ void unpack2(ull v, float& lo, float& hi) {
    asm("mov.b64 {%0, %1}, %2;" : "=f"(lo), "=f"(hi) : "l"(v));
}
#define FMA2(d, a, b, c) asm("fma.rn.f32x2 %0, %1, %2, %3;" : "=l"(d) : "l"(a), "l"(b), "l"(c))
#define MUL2(d, a, b)    asm("mul.rn.f32x2 %0, %1, %2;"     : "=l"(d) : "l"(a), "l"(b))
#define ADD2(d, a, b)    asm("add.rn.f32x2 %0, %1, %2;"     : "=l"(d) : "l"(a), "l"(b))
#define XOR64(d, a, b)   asm("xor.b64 %0, %1, %2;"          : "=l"(d) : "l"(a), "l"(b))

// ---------------------------------------------------------------------------
// GEMM half-K body (R7-proven staging): C[m,n] = [bias[n]] + sum_{c in K-half}
// A[m,c]*W[n,c].  Tile 32x32, 128 threads, 2m x 4n per thread, BK=32 x 4 iters.
// A pre-splatted to (a,a) pairs; inner kk = 2x LDS.64 bcast + 1x LDS.128 + 4 FMA2.
// ---------------------------------------------------------------------------
#define GK 256

__device__ __forceinline__ void gemm_body_half(
    const float* __restrict__ A, const float* __restrict__ W,
    const float* __restrict__ bias, float* __restrict__ C, int kbase)
{
    __shared__ ull   As2[32][33];   // [k][m] (a,a) pairs
    __shared__ float Ws [32][36];   // [k][n]

    const int tid = threadIdx.x;       // 0..127
    const int m0 = blockIdx.y * 32;
    const int n0 = blockIdx.x * 32;
    const int r  = tid >> 3;           // 0..15
    const int c  = tid & 7;            // 0..7

    const float* Ap = A + (m0 + r) * GK + kbase + 4 * c;
    const float* Wp = W + (n0 + r) * GK + kbase + 4 * c;

    ull acc00 = 0ull, acc01 = 0ull, acc10 = 0ull, acc11 = 0ull;

    float4 a4a = *reinterpret_cast<const float4*>(Ap);
    float4 a4b = *reinterpret_cast<const float4*>(Ap + 16 * GK);
    float4 w4a = *reinterpret_cast<const float4*>(Wp);
    float4 w4b = *reinterpret_cast<const float4*>(Wp + 16 * GK);

#pragma unroll 1
    for (int it = 0; it < 4; it++) {
        __syncthreads();
        As2[4*c + 0][r]      = pack2(a4a.x, a4a.x);
        As2[4*c + 1][r]      = pack2(a4a.y, a4a.y);
        As2[4*c + 2][r]      = pack2(a4a.z, a4a.z);
        As2[4*c + 3][r]      = pack2(a4a.w, a4a.w);
        As2[4*c + 0][16 + r] = pack2(a4b.x, a4b.x);
        As2[4*c + 1][16 + r] = pack2(a4b.y, a4b.y);
        As2[4*c + 2][16 + r] = pack2(a4b.z, a4b.z);
        As2[4*c + 3][16 + r] = pack2(a4b.w, a4b.w);
        Ws[4*c + 0][r]      = w4a.x; Ws[4*c + 1][r]      = w4a.y;
        Ws[4*c + 2][r]      = w4a.z; Ws[4*c + 3][r]      = w4a.w;
        Ws[4*c + 0][16 + r] = w4b.x; Ws[4*c + 1][16 + r] = w4b.y;
        Ws[4*c + 2][16 + r] = w4b.z; Ws[4*c + 3][16 + r] = w4b.w;
        __syncthreads();
        if (it < 3) {
            a4a = *reinterpret_cast<const float4*>(Ap + (it + 1) * 32);
            a4b = *reinterpret_cast<const float4*>(Ap + 16 * GK + (it + 1) * 32);
            w4a = *reinterpret_cast<const float4*>(Wp + (it + 1) * 32);
            w4b = *reinterpret_cast<const float4*>(Wp + 16 * GK + (it + 1) * 32);
        }
#pragma unroll
        for (int kk = 0; kk < 32; kk++) {
            ull a0 = As2[kk][2 * r];
            ull a1 = As2[kk][2 * r + 1];
            const ull* wr = reinterpret_cast<const ull*>(&Ws[kk][4 * c]);
            ull w01 = wr[0], w23 = wr[1];
            FMA2(acc00, a0, w01, acc00);
            FMA2(acc01, a0, w23, acc01);
            FMA2(acc10, a1, w01, acc10);
            FMA2(acc11, a1, w23, acc11);
        }
    }

    float4 b4 = make_float4(0.f, 0.f, 0.f, 0.f);
    if (bias) b4 = *reinterpret_cast<const float4*>(bias + n0 + 4 * c);
    float x0, x1, x2, x3;
    unpack2(acc00, x0, x1); unpack2(acc01, x2, x3);
    {
        float4 o; o.x = x0 + b4.x; o.y = x1 + b4.y; o.z = x2 + b4.z; o.w = x3 + b4.w;
        *reinterpret_cast<float4*>(&C[(m0 + 2*r) * HID + n0 + 4*c]) = o;
    }
    unpack2(acc10, x0, x1); unpack2(acc11, x2, x3);
    {
        float4 o; o.x = x0 + b4.x; o.y = x1 + b4.y; o.z = x2 + b4.z; o.w = x3 + b4.w;
        *reinterpret_cast<float4*>(&C[(m0 + 2*r + 1) * HID + n0 + 4*c]) = o;
    }
}

// QKV: blockIdx.z in [0,6): z = bz>>1 selects q/k/v, bz&1 selects K-half.
__global__ void __launch_bounds__(128)
gemm_qkv_kernel(const float* __restrict__ x,
                const float* __restrict__ wq, const float* __restrict__ bq,
                const float* __restrict__ wk, const float* __restrict__ bk,
                const float* __restrict__ wv, const float* __restrict__ bv)
{
    const int bz = blockIdx.z;
    const int z = bz >> 1;
    const int half = bz & 1;
    const float* W = (z == 0) ? wq : ((z == 1) ? wk : wv);
    const float* b = (z == 0) ? bq : ((z == 1) ? bk : bv);
    float* C = (half ? g_qkvB : g_qkvA) + z * (S_LEN * HID);
    gemm_body_half(x, W, half ? nullptr : b, C, half * 128);
}

__global__ void __launch_bounds__(128)
gemm_out_kernel(const float* __restrict__ wo, const float* __restrict__ bo)
{
    const int half = blockIdx.z;
    float* C = half ? g_outB : g_outA;
    gemm_body_half(g_ctx, wo, half ? nullptr : bo, C, half * 128);
}

// Final reduce: out = g_outA + g_outB  (131072 floats = 32768 float4)
__global__ void __launch_bounds__(256)
add_out_kernel(float* __restrict__ out)
{
    const int idx = (blockIdx.x * 256 + threadIdx.x) * 4;
    float4 a = *reinterpret_cast<const float4*>(g_outA + idx);
    float4 b = *reinterpret_cast<const float4*>(g_outB + idx);
    float4 o; o.x = a.x + b.x; o.y = a.y + b.y; o.z = a.z + b.z; o.w = a.w + b.w;
    *reinterpret_cast<float4*>(out + idx) = o;
}

// ---------------------------------------------------------------------------
// Attention. Grid: (32 i-tiles, 8 heads), 256 threads = 8 warps x 32 d.
// Each warp owns TWO i-rows sharing one V load. q/k/v are read as the sum of
// the two split-K partials (projection is linear).
// logit X_j = K0*cos(theta0 - j*omega), K0 = SCALE*sigmoid(k) <= 0.177.
// Weight p = 1 + b*X + X^2/2, minimax slope b = 1 + K0^2/8 (|err|<=K0^3/24).
// Numerator via Chebyshev recurrence; sum V precomputed; denominator via
// closed-form Dirichlet sums D1, D2.
// ---------------------------------------------------------------------------
#define ATTN_SMEM (256 * 32 * 8 + 8 * 32 * 8)   // V pairs + partial sums

__global__ void __launch_bounds__(256)
attn_kernel()
{
    extern __shared__ ull Vs[];           // [256][32] j-pairs, then Ps[8][32]
    ull* Ps = Vs + 256 * 32;
    const int h   = blockIdx.y;
    const int tid = threadIdx.x;
    const int d   = tid & 31;
    const int r   = tid >> 5;             // warp id
    const int i0  = blockIdx.x * 16 + 2 * r;
    const int i1  = i0 + 1;

    const float* gqA = g_qkvA;
    const float* gkA = g_qkvA + S_LEN * HID;
    const float* gvA = g_qkvA + 2 * S_LEN * HID;
    const float* gqB = g_qkvB;
    const float* gkB = g_qkvB + S_LEN * HID;
    const float* gvB = g_qkvB + 2 * S_LEN * HID;

    // Stage V[h,:,:] (sum of partials) as (even,odd) pairs + partial sums.
    {
        float sve = 0.0f, svo = 0.0f;
#pragma unroll 4
        for (int kk = 0; kk < 32; kk++) {
            int k = r * 32 + kk;
            int i0e = (2 * k) * HID + h * HD + d;
            int i0o = (2 * k + 1) * HID + h * HD + d;
            float v0 = gvA[i0e] + gvB[i0e];
            float v1 = gvA[i0o] + gvB[i0o];
            Vs[k * 32 + d] = pack2(v0, v1);
            sve += v0; svo += v1;
        }
        Ps[r * 32 + d] = pack2(sve, svo);
    }

    const int col = h * HD + d;

    // Per-i wave state
    ull X[2], NX[2], C2v[2], B2[2], acc[2];
    float sumw[2];
#pragma unroll
    for (int u = 0; u < 2; u++) {
        const int i = (u == 0) ? i0 : i1;
        const int idx = i * HID + col;
        const float qv = gqA[idx] + gqB[idx];
        const float kv = gkA[idx] + gkB[idx];
        const float vv = gvA[idx] + gvB[idx];

        const float omega = PI_F / (1.0f + expf(-qv));   // sigmoid(q)*pi
        const float amp   = 1.0f / (1.0f + expf(-kv));   // sigmoid(k)
        const float phase = PI_F * tanhf(vv);            // tanh(v)*pi
        const float K0    = SCALE_F * amp;
        const float bmin  = 1.0f + K0 * K0 * 0.125f;     // minimax slope

        const float th0 = omega * (float)i + phase;      // theta at j=0
        float s0, c0, sw, cw;
        sincosf(th0, &s0, &c0);
        sincosf(omega, &sw, &cw);
        const float c2w = cw * cw - sw * sw;             // cos(2w)
        const float s2w = 2.0f * sw * cw;                // sin(2w)
        // X_0 lanes: j=0, j=1 ; X_{-1} lanes: j=-2, j=-1
        const float x0e = K0 * c0;
        const float x0o = K0 * (c0 * cw + s0 * sw);
        const float xme = K0 * (c0 * c2w - s0 * s2w);
        const float xmo = K0 * (c0 * cw - s0 * sw);

        // Denominator: sum_j (1 + b*x_j + x_j^2/2), j=0..511
        const float sb2 = sinf(0.5f * omega);
        const float D1 = cosf(th0 - 255.5f * omega) * sinf(256.0f * omega) / sb2;
        const float D2 = cosf(2.0f * th0 - 511.0f * omega) * sinf(512.0f * omega) / sw;
        sumw[u] = 512.0f + bmin * K0 * D1
                + 0.5f * K0 * K0 * (256.0f + 0.5f * D2);

        X[u]   = pack2(x0e, x0o);
        NX[u]  = pack2(-xme, -xmo);
        C2v[u] = pack2(2.0f * c2w, 2.0f * c2w);
        B2[u]  = pack2(bmin, bmin);
        acc[u] = 0ull;
    }

    const ull SMASK = 0x8000000080000000ULL;
    ull P2 = pack2(0.5f, 0.5f);

    __syncthreads();

    // sum of V over all j for this (h,d)
    float svE = 0.0f, svO = 0.0f;
#pragma unroll
    for (int g = 0; g < 8; g++) {
        float pe, po;
        unpack2(Ps[g * 32 + d], pe, po);
        svE += pe; svO += po;
    }

    const ull* vp = Vs + d;

#pragma unroll 8
    for (int k = 0; k < 256; k++) {
        ull V2 = vp[k * 32];
#pragma unroll
        for (int u = 0; u < 2; u++) {
            ull rr, t, Xn;
            // p-1 = x*(b + x/2)
            FMA2(rr, X[u], P2, B2[u]);
            MUL2(t, X[u], V2);
            FMA2(acc[u], rr, t, acc[u]);
            // Chebyshev: X_{k+1} = 2cos(2w)*X_k + (-X_{k-1})
            FMA2(Xn, C2v[u], X[u], NX[u]);
            XOR64(NX[u], X[u], SMASK);
            X[u] = Xn;
        }
    }

    float ae, ao;
    unpack2(acc[0], ae, ao);
    g_ctx[i0 * HID + col] = (svE + svO + ae + ao) / sumw[0];
    unpack2(acc[1], ae, ao);
    g_ctx[i1 * HID + col] = (svE + svO + ae + ao) / sumw[1];
}

// ---------------------------------------------------------------------------
extern "C" void kernel_launch(void* const* d_in, const int* in_sizes, int n_in,
                              void* d_out, int out_size)
{
    const float* x  = (const float*)d_in[0];
    const float* wq = (const float*)d_in[1];
    const float* bq = (const float*)d_in[2];
    const float* wk = (const float*)d_in[3];
    const float* bk = (const float*)d_in[4];
    const float* wv = (const float*)d_in[5];
    const float* bv = (const float*)d_in[6];
    const float* wo = (const float*)d_in[7];
    const float* bo = (const float*)d_in[8];
    float* out = (float*)d_out;

    cudaFuncSetAttribute(attn_kernel, cudaFuncAttributeMaxDynamicSharedMemorySize, ATTN_SMEM);

    // QKV projections, split-K=2: (8 n) x (16 m) x 6 = 768 blocks of 128 threads
    gemm_qkv_kernel<<<dim3(HID / 32, S_LEN / 32, 6), 128>>>(x, wq, bq, wk, bk, wv, bv);

    // Attention: 32 i-tiles x 8 heads (reduces qkv partials on the fly)
    attn_kernel<<<dim3(S_LEN / 16, NH), 256, ATTN_SMEM>>>();

    // Output projection, split-K=2: 256 blocks, then reduce
    gemm_out_kernel<<<dim3(HID / 32, S_LEN / 32, 2), 128>>>(wo, bo);
    add_out_kernel<<<S_LEN * HID / 1024, 256>>>(out);
}

// round 14
// speedup vs baseline: 1.1515x; 1.0424x over previous
#include <cuda_runtime.h>
#include <math.h>

#define S_LEN 512
#define HID   256
#define NH    8
#define HD    32
#define SCALE_F 0.17677669529663687f   // 1/sqrt(32)
#define PI_F    3.14159265358979323846f
#define GK     256
#define NBLK   256u

// Scratch (no allocations allowed)
__device__ float g_qkv[3 * S_LEN * HID];
__device__ float g_ctx[S_LEN * HID];
__device__ float g_outA[S_LEN * HID];
__device__ float g_outB[S_LEN * HID];
__device__ unsigned g_bar[4];   // monotonic phase counters (replay-safe)

typedef unsigned long long ull;

__device__ __forceinline__ ull pack2(float lo, float hi) {
    ull r; asm("mov.b64 %0, {%1, %2};" : "=l"(r) : "f"(lo), "f"(hi)); return r;
}
__device__ __forceinline__ void unpack2(ull v, float& lo, float& hi) {
    asm("mov.b64 {%0, %1}, %2;" : "=f"(lo), "=f"(hi) : "l"(v));
}
#define FMA2(d, a, b, c) asm("fma.rn.f32x2 %0, %1, %2, %3;" : "=l"(d) : "l"(a), "l"(b), "l"(c))
#define MUL2(d, a, b)    asm("mul.rn.f32x2 %0, %1, %2;"     : "=l"(d) : "l"(a), "l"(b))
#define XOR64(d, a, b)   asm("xor.b64 %0, %1, %2;"          : "=l"(d) : "l"(a), "l"(b))

// Grid-wide barrier: monotonic counter, target = next multiple of NBLK.
// Works across CUDA-graph replays without reset (wraps after ~16M launches).
__device__ __forceinline__ void grid_sync(int b) {
    __syncthreads();
    if (threadIdx.x == 0) {
        __threadfence();
        unsigned v = atomicAdd(&g_bar[b], 1u);
        unsigned target = (v & ~(NBLK - 1u)) + NBLK;
        volatile unsigned* p = &g_bar[b];
        while (*p < target) {}
        __threadfence();
    }
    __syncthreads();
}

#define FUSED_SMEM (256 * 32 * 8 + 8 * 32 * 8)   // 67584 B (attn is the max user)

__global__ void __launch_bounds__(256, 2)
fused_kernel(const float* __restrict__ x,
             const float* __restrict__ wq, const float* __restrict__ bq,
             const float* __restrict__ wk, const float* __restrict__ bk,
             const float* __restrict__ wv, const float* __restrict__ bv,
             const float* __restrict__ wo, const float* __restrict__ bo,
             float* __restrict__ out)
{
    extern __shared__ char sm[];
    const int tid = threadIdx.x;
    const int bid = blockIdx.x;

    // =====================================================================
    // Phase A: QKV projections. 192 tiles of 64m x 32n, full K=256.
    // 256 threads: 2m x 4n per thread; inner kk = 2 LDS.64 bcast + 1 LDS.128
    // + 4 FMA2.
    // =====================================================================
    {
        ull*   As2 = reinterpret_cast<ull*>(sm);                 // [32][66]
        float* Ws  = reinterpret_cast<float*>(sm + 32 * 66 * 8); // [32][36]

        if (bid < 192) {
            const int z   = bid >> 6;
            const int rem = bid & 63;
            const float* W  = (z == 0) ? wq : ((z == 1) ? wk : wv);
            const float* bi = (z == 0) ? bq : ((z == 1) ? bk : bv);
            float* C = g_qkv + z * (S_LEN * HID);
            const int m0 = (rem >> 3) * 64;
            const int n0 = (rem & 7) * 32;

            const int tm = tid >> 3;          // 0..31 -> rows 2tm, 2tm+1
            const int tn = tid & 7;           // 0..7  -> cols 4tn..+3
            const int sr = tid >> 2;          // A staging row 0..63
            const int sq = tid & 3;           // A staging k-group
            const int vr = tid >> 3;          // W staging row 0..31
            const int vq = tid & 7;           // W staging k-group

            const float* Ap = x + (m0 + sr) * GK + 4 * sq;
            const float* Wp = W + (n0 + vr) * GK + 4 * vq;

            ull acc00 = 0ull, acc01 = 0ull, acc10 = 0ull, acc11 = 0ull;

            float4 aA = *reinterpret_cast<const float4*>(Ap);
            float4 aB = *reinterpret_cast<const float4*>(Ap + 16);
            float4 w4 = *reinterpret_cast<const float4*>(Wp);

#pragma unroll 1
            for (int it = 0; it < 8; it++) {
                __syncthreads();
                As2[(4 * sq + 0) * 66 + sr] = pack2(aA.x, aA.x);
                As2[(4 * sq + 1) * 66 + sr] = pack2(aA.y, aA.y);
                As2[(4 * sq + 2) * 66 + sr] = pack2(aA.z, aA.z);
                As2[(4 * sq + 3) * 66 + sr] = pack2(aA.w, aA.w);
                As2[(16 + 4 * sq + 0) * 66 + sr] = pack2(aB.x, aB.x);
                As2[(16 + 4 * sq + 1) * 66 + sr] = pack2(aB.y, aB.y);
                As2[(16 + 4 * sq + 2) * 66 + sr] = pack2(aB.z, aB.z);
                As2[(16 + 4 * sq + 3) * 66 + sr] = pack2(aB.w, aB.w);
                Ws[(4 * vq + 0) * 36 + vr] = w4.x;
                Ws[(4 * vq + 1) * 36 + vr] = w4.y;
                Ws[(4 * vq + 2) * 36 + vr] = w4.z;
                Ws[(4 * vq + 3) * 36 + vr] = w4.w;
                __syncthreads();
                if (it < 7) {
                    aA = *reinterpret_cast<const float4*>(Ap + (it + 1) * 32);
                    aB = *reinterpret_cast<const float4*>(Ap + 16 + (it + 1) * 32);
                    w4 = *reinterpret_cast<const float4*>(Wp + (it + 1) * 32);
                }
#pragma unroll
                for (int kk = 0; kk < 32; kk++) {
                    ull a0 = As2[kk * 66 + 2 * tm];
                    ull a1 = As2[kk * 66 + 2 * tm + 1];
                    ulonglong2 w = *reinterpret_cast<const ulonglong2*>(Ws + kk * 36 + 4 * tn);
                    FMA2(acc00, a0, w.x, acc00);
                    FMA2(acc01, a0, w.y, acc01);
                    FMA2(acc10, a1, w.x, acc10);
                    FMA2(acc11, a1, w.y, acc11);
                }
            }

            float4 b4 = *reinterpret_cast<const float4*>(bi + n0 + 4 * tn);
            float x0, x1, x2, x3;
            unpack2(acc00, x0, x1); unpack2(acc01, x2, x3);
            {
                float4 o; o.x = x0 + b4.x; o.y = x1 + b4.y; o.z = x2 + b4.z; o.w = x3 + b4.w;
                *reinterpret_cast<float4*>(&C[(m0 + 2 * tm) * HID + n0 + 4 * tn]) = o;
            }
            unpack2(acc10, x0, x1); unpack2(acc11, x2, x3);
            {
                float4 o; o.x = x0 + b4.x; o.y = x1 + b4.y; o.z = x2 + b4.z; o.w = x3 + b4.w;
                *reinterpret_cast<float4*>(&C[(m0 + 2 * tm + 1) * HID + n0 + 4 * tn]) = o;
            }
        }
    }
    grid_sync(0);

    // =====================================================================
    // Phase B: attention. 256 items = (32 i-tiles) x (8 heads), item = bid.
    // Each warp owns TWO i-rows sharing one V load.
    // =====================================================================
    {
        ull* Vs = reinterpret_cast<ull*>(sm);   // [256][32] j-pairs
        ull* Ps = Vs + 256 * 32;                // [8][32] partial V sums
        const int h  = bid & 7;
        const int ix = bid >> 3;
        const int d  = tid & 31;
        const int r  = tid >> 5;
        const int i0 = ix * 16 + 2 * r;
        const int i1 = i0 + 1;

        const float* gq = g_qkv;
        const float* gk = g_qkv + S_LEN * HID;
        const float* gv = g_qkv + 2 * S_LEN * HID;

        {
            float sve = 0.0f, svo = 0.0f;
#pragma unroll 4
            for (int kk = 0; kk < 32; kk++) {
                int k = r * 32 + kk;
                float v0 = gv[(2 * k)     * HID + h * HD + d];
                float v1 = gv[(2 * k + 1) * HID + h * HD + d];
                Vs[k * 32 + d] = pack2(v0, v1);
                sve += v0; svo += v1;
            }
            Ps[r * 32 + d] = pack2(sve, svo);
        }

        const int col = h * HD + d;

        ull X[2], NX[2], C2v[2], B2[2], acc[2];
        float sumw[2];
#pragma unroll
        for (int u = 0; u < 2; u++) {
            const int i = (u == 0) ? i0 : i1;
            const int idx = i * HID + col;
            const float qv = gq[idx];
            const float kv = gk[idx];
            const float vv = gv[idx];

            const float omega = PI_F / (1.0f + expf(-qv));   // sigmoid(q)*pi
            const float amp   = 1.0f / (1.0f + expf(-kv));   // sigmoid(k)
            const float phase = PI_F * tanhf(vv);            // tanh(v)*pi
            const float K0    = SCALE_F * amp;
            const float bmin  = 1.0f + K0 * K0 * 0.125f;     // minimax slope

            const float th0 = omega * (float)i + phase;
            float s0, c0, sw, cw;
            sincosf(th0, &s0, &c0);
            sincosf(omega, &sw, &cw);
            const float c2w = cw * cw - sw * sw;
            const float s2w = 2.0f * sw * cw;
            const float x0e = K0 * c0;
            const float x0o = K0 * (c0 * cw + s0 * sw);
            const float xme = K0 * (c0 * c2w - s0 * s2w);
            const float xmo = K0 * (c0 * cw - s0 * sw);

            // Denominator: sum_j (1 + b*x_j + x_j^2/2), closed-form Dirichlet
            const float sb2 = sinf(0.5f * omega);
            const float D1 = cosf(th0 - 255.5f * omega) * sinf(256.0f * omega) / sb2;
            const float D2 = cosf(2.0f * th0 - 511.0f * omega) * sinf(512.0f * omega) / sw;
            sumw[u] = 512.0f + bmin * K0 * D1
                    + 0.5f * K0 * K0 * (256.0f + 0.5f * D2);

            X[u]   = pack2(x0e, x0o);
            NX[u]  = pack2(-xme, -xmo);
            C2v[u] = pack2(2.0f * c2w, 2.0f * c2w);
            B2[u]  = pack2(bmin, bmin);
            acc[u] = 0ull;
        }

        const ull SMASK = 0x8000000080000000ULL;
        ull P2 = pack2(0.5f, 0.5f);

        __syncthreads();

        float svE = 0.0f, svO = 0.0f;
#pragma unroll
        for (int g = 0; g < 8; g++) {
            float pe, po;
            unpack2(Ps[g * 32 + d], pe, po);
            svE += pe; svO += po;
        }

        const ull* vp = Vs + d;

#pragma unroll 8
        for (int k = 0; k < 256; k++) {
            ull V2 = vp[k * 32];
#pragma unroll
            for (int u = 0; u < 2; u++) {
                ull rr, t2, Xn;
                FMA2(rr, X[u], P2, B2[u]);        // b + x/2
                MUL2(t2, X[u], V2);
                FMA2(acc[u], rr, t2, acc[u]);     // += x*(b+x/2)*V
                FMA2(Xn, C2v[u], X[u], NX[u]);    // Chebyshev step
                XOR64(NX[u], X[u], SMASK);
                X[u] = Xn;
            }
        }

        float ae, ao;
        unpack2(acc[0], ae, ao);
        g_ctx[i0 * HID + col] = (svE + svO + ae + ao) / sumw[0];
        unpack2(acc[1], ae, ao);
        g_ctx[i1 * HID + col] = (svE + svO + ae + ao) / sumw[1];
    }
    grid_sync(1);

    // =====================================================================
    // Phase C: out projection, split-K=2. 256 jobs = (16m x 8n tiles) x 2
    // halves; tile 32m x 32n, K-half = 128. 2m x 2n per thread.
    // =====================================================================
    {
        ull*   As2 = reinterpret_cast<ull*>(sm);                 // [32][34]
        float* Ws  = reinterpret_cast<float*>(sm + 32 * 34 * 8); // [32][36]

        const int half = bid >> 7;
        const int rem  = bid & 127;
        const int m0 = (rem >> 3) * 32;
        const int n0 = (rem & 7) * 32;
        const int kb = half * 128;
        float* C = half ? g_outB : g_outA;

        const int tm = tid >> 4;          // 0..15 -> rows 2tm, 2tm+1
        const int tn = tid & 15;          // 0..15 -> cols 2tn, 2tn+1
        const int sr = tid >> 3;          // staging row 0..31
        const int sq = tid & 7;           // staging k-group

        const float* Ap = g_ctx + (m0 + sr) * GK + kb + 4 * sq;
        const float* Wp = wo    + (n0 + sr) * GK + kb + 4 * sq;

        ull acc0 = 0ull, acc1 = 0ull;

        float4 a4 = *reinterpret_cast<const float4*>(Ap);
        float4 w4 = *reinterpret_cast<const float4*>(Wp);

#pragma unroll 1
        for (int it = 0; it < 4; it++) {
            __syncthreads();
            As2[(4 * sq + 0) * 34 + sr] = pack2(a4.x, a4.x);
            As2[(4 * sq + 1) * 34 + sr] = pack2(a4.y, a4.y);
            As2[(4 * sq + 2) * 34 + sr] = pack2(a4.z, a4.z);
            As2[(4 * sq + 3) * 34 + sr] = pack2(a4.w, a4.w);
            Ws[(4 * sq + 0) * 36 + sr] = w4.x;
            Ws[(4 * sq + 1) * 36 + sr] = w4.y;
            Ws[(4 * sq + 2) * 36 + sr] = w4.z;
            Ws[(4 * sq + 3) * 36 + sr] = w4.w;
            __syncthreads();
            if (it < 3) {
                a4 = *reinterpret_cast<const float4*>(Ap + (it + 1) * 32);
                w4 = *reinterpret_cast<const float4*>(Wp + (it + 1) * 32);
            }
#pragma unroll
            for (int kk = 0; kk < 32; kk++) {
                ulonglong2 ap = *reinterpret_cast<const ulonglong2*>(As2 + kk * 34 + 2 * tm);
                ull w01 = *reinterpret_cast<const ull*>(Ws + kk * 36 + 2 * tn);
                FMA2(acc0, ap.x, w01, acc0);
                FMA2(acc1, ap.y, w01, acc1);
            }
        }

        *reinterpret_cast<ull*>(&C[(m0 + 2 * tm)     * HID + n0 + 2 * tn]) = acc0;
        *reinterpret_cast<ull*>(&C[(m0 + 2 * tm + 1) * HID + n0 + 2 * tn]) = acc1;
    }
    grid_sync(2);

    // =====================================================================
    // Phase D: out = outA + outB + bias
    // =====================================================================
    {
        const int idx = bid * 256 + tid;            // 0..65535
        if (idx < (S_LEN * HID) / 4) {
            float4 a = *reinterpret_cast<const float4*>(g_outA + idx * 4);
            float4 b = *reinterpret_cast<const float4*>(g_outB + idx * 4);
            float4 c = *reinterpret_cast<const float4*>(bo + ((idx * 4) & 255));
            float4 o;
            o.x = a.x + b.x + c.x; o.y = a.y + b.y + c.y;
            o.z = a.z + b.z + c.z; o.w = a.w + b.w + c.w;
            *reinterpret_cast<float4*>(out + idx * 4) = o;
        }
    }
}

// ---------------------------------------------------------------------------
extern "C" void kernel_launch(void* const* d_in, const int* in_sizes, int n_in,
                              void* d_out, int out_size)
{
    const float* x  = (const float*)d_in[0];
    const float* wq = (const float*)d_in[1];
    const float* bq = (const float*)d_in[2];
    const float* wk = (const float*)d_in[3];
    const float* bk = (const float*)d_in[4];
    const float* wv = (const float*)d_in[5];
    const float* bv = (const float*)d_in[6];
    const float* wo = (const float*)d_in[7];
    const float* bo = (const float*)d_in[8];
    float* out = (float*)d_out;

    cudaFuncSetAttribute(fused_kernel, cudaFuncAttributeMaxDynamicSharedMemorySize, FUSED_SMEM);
    fused_kernel<<<NBLK, 256, FUSED_SMEM>>>(x, wq, bq, wk, bk, wv, bv, wo, bo, out);
}